// round 1
// baseline (speedup 1.0000x reference)
#include <cuda_runtime.h>
#include <cuda_bf16.h>

#define PATCH 16
#define EMBED 384
#define IMG_B 64
#define IMG_HW 224
#define GRID_HW 14            // 224/16
#define NPATCH 196            // 14*14
#define M_TOTAL (IMG_B * NPATCH)   // 12544
#define K_TOTAL 768           // 3*16*16
#define CHAN_STRIDE (IMG_HW * IMG_HW)  // 50176

// ---------------------------------------------------------------------------
// Entropy kernel: one block per patch, 256 threads (one per pixel).
// ---------------------------------------------------------------------------
__global__ __launch_bounds__(256) void entropy_kernel(
    const float* __restrict__ img, float* __restrict__ ent) {
    const int m = blockIdx.x;
    const int b = m / NPATCH;
    const int pidx = m % NPATCH;
    const int gh = pidx / GRID_HW;
    const int gw = pidx % GRID_HW;
    const int tid = threadIdx.x;

    __shared__ int hist[32];
    if (tid < 32) hist[tid] = 0;
    __syncthreads();

    const int i = tid >> 4;      // row within patch
    const int j = tid & 15;      // col within patch
    const size_t base = ((size_t)b * 3) * CHAN_STRIDE
                      + (size_t)(gh * PATCH + i) * IMG_HW + (gw * PATCH + j);
    const float c0 = img[base];
    const float c1 = img[base + CHAN_STRIDE];
    const float c2 = img[base + 2 * CHAN_STRIDE];
    const float g = (c0 + c1 + c2) / 3.0f;
    int q = (int)fminf(fmaxf(g * 31.0f, 0.0f), 31.0f);
    atomicAdd(&hist[q], 1);
    __syncthreads();

    if (tid < 32) {
        float p = (float)hist[tid] * (1.0f / 256.0f);
        float t = p * log2f(p + 1e-10f);
        #pragma unroll
        for (int o = 16; o; o >>= 1) t += __shfl_xor_sync(0xffffffffu, t, o);
        if (tid == 0) ent[m] = -t * 0.2f;   // / log2(32)
    }
}

// ---------------------------------------------------------------------------
// Patch-embed GEMM: C[M=12544, N=384] = A[M,768] * W[N,768]^T + bias
// A gathered directly from NCHW images (patch extraction fused).
// Tile: 128x128x32, 256 threads, 8x8 register tile per thread.
// ---------------------------------------------------------------------------
__global__ __launch_bounds__(256, 2) void gemm_kernel(
    const float* __restrict__ img, const float* __restrict__ w,
    const float* __restrict__ bias, float* __restrict__ out) {
    const int tid = threadIdx.x;
    const int bn = blockIdx.x;   // 0..2   (N blocks of 128)
    const int bm = blockIdx.y;   // 0..97  (M blocks of 128)

    __shared__ float As[128][36];   // [m][k], pad 36 for conflict-free access
    __shared__ float Bs[128][36];   // [n][k]

    const int r0 = tid >> 3;           // 0..31 : row within 32-row group
    const int kq = (tid & 7) << 2;     // 0,4,...,28 : k offset (float4)

    // Precompute image base addresses for the 4 A-rows this thread loads.
    size_t abase[4];
    #pragma unroll
    for (int l = 0; l < 4; l++) {
        int m = bm * 128 + r0 + 32 * l;
        int b = m / NPATCH;
        int pidx = m % NPATCH;
        int gh = pidx / GRID_HW;
        int gw = pidx % GRID_HW;
        abase[l] = ((size_t)b * 3) * CHAN_STRIDE
                 + (size_t)(gh * PATCH) * IMG_HW + (size_t)(gw * PATCH);
    }
    const int wrow0 = bn * 128;

    float acc[8][8];
    #pragma unroll
    for (int r = 0; r < 8; r++)
        #pragma unroll
        for (int c = 0; c < 8; c++) acc[r][c] = 0.0f;

    const int ty = tid >> 4;   // 0..15
    const int tx = tid & 15;   // 0..15

    for (int k0 = 0; k0 < K_TOTAL; k0 += 32) {
        const int k = k0 + kq;
        const int ch  = k >> 8;         // channel
        const int rem = k & 255;
        const int pi  = rem >> 4;       // row within patch
        const int pj  = rem & 15;       // col within patch
        #pragma unroll
        for (int l = 0; l < 4; l++) {
            float4 av = *(const float4*)(img + abase[l]
                          + (size_t)ch * CHAN_STRIDE + pi * IMG_HW + pj);
            *(float4*)&As[r0 + 32 * l][kq] = av;
            float4 bv = *(const float4*)(w + (size_t)(wrow0 + r0 + 32 * l) * K_TOTAL + k);
            *(float4*)&Bs[r0 + 32 * l][kq] = bv;
        }
        __syncthreads();

        #pragma unroll
        for (int kk = 0; kk < 32; kk += 2) {
            float2 a2[8], b2[8];
            #pragma unroll
            for (int r = 0; r < 8; r++) a2[r] = *(const float2*)&As[ty + 16 * r][kk];
            #pragma unroll
            for (int c = 0; c < 8; c++) b2[c] = *(const float2*)&Bs[tx + 16 * c][kk];
            #pragma unroll
            for (int r = 0; r < 8; r++)
                #pragma unroll
                for (int c = 0; c < 8; c++) {
                    acc[r][c] = fmaf(a2[r].x, b2[c].x, acc[r][c]);
                    acc[r][c] = fmaf(a2[r].y, b2[c].y, acc[r][c]);
                }
        }
        __syncthreads();
    }

    // Epilogue: add bias, write pre-LN x.
    #pragma unroll
    for (int r = 0; r < 8; r++) {
        const int m = bm * 128 + ty + 16 * r;
        #pragma unroll
        for (int c = 0; c < 8; c++) {
            const int n = bn * 128 + tx + 16 * c;
            out[(size_t)m * EMBED + n] = acc[r][c] + bias[n];
        }
    }
}

// ---------------------------------------------------------------------------
// LayerNorm (in place): one block (128 threads) per row of 384.
// Two-pass: mean, then biased var of residuals (matches torch/jnp semantics).
// ---------------------------------------------------------------------------
__global__ __launch_bounds__(128) void ln_kernel(
    float* __restrict__ x, const float* __restrict__ gamma,
    const float* __restrict__ beta) {
    const int row = blockIdx.x;
    const int tid = threadIdx.x;
    float* p = x + (size_t)row * EMBED;

    const float v0 = p[tid];
    const float v1 = p[tid + 128];
    const float v2 = p[tid + 256];

    __shared__ float red[4];
    float s = v0 + v1 + v2;
    #pragma unroll
    for (int o = 16; o; o >>= 1) s += __shfl_xor_sync(0xffffffffu, s, o);
    if ((tid & 31) == 0) red[tid >> 5] = s;
    __syncthreads();
    const float mu = (red[0] + red[1] + red[2] + red[3]) * (1.0f / EMBED);

    const float d0 = v0 - mu, d1 = v1 - mu, d2 = v2 - mu;
    float sq = d0 * d0 + d1 * d1 + d2 * d2;
    __syncthreads();   // red[] reuse
    #pragma unroll
    for (int o = 16; o; o >>= 1) sq += __shfl_xor_sync(0xffffffffu, sq, o);
    if ((tid & 31) == 0) red[tid >> 5] = sq;
    __syncthreads();
    const float var = (red[0] + red[1] + red[2] + red[3]) * (1.0f / EMBED);
    const float sc = rsqrtf(var + 1e-5f);

    p[tid]       = d0 * sc * gamma[tid]       + beta[tid];
    p[tid + 128] = d1 * sc * gamma[tid + 128] + beta[tid + 128];
    p[tid + 256] = d2 * sc * gamma[tid + 256] + beta[tid + 256];
}

// ---------------------------------------------------------------------------
extern "C" void kernel_launch(void* const* d_in, const int* in_sizes, int n_in,
                              void* d_out, int out_size) {
    const float* images = (const float*)d_in[0];
    const float* proj_w = (const float*)d_in[1];
    const float* proj_b = (const float*)d_in[2];
    const float* ln_g   = (const float*)d_in[3];
    const float* ln_b   = (const float*)d_in[4];
    float* out = (float*)d_out;

    float* x   = out;                                   // (B, N, D) f32
    float* ent = out + (size_t)M_TOTAL * EMBED;         // (B, N)    f32

    entropy_kernel<<<M_TOTAL, 256>>>(images, ent);
    gemm_kernel<<<dim3(EMBED / 128, M_TOTAL / 128), 256>>>(images, proj_w, proj_b, x);
    ln_kernel<<<M_TOTAL, 128>>>(x, ln_g, ln_b);
}

// round 3
// speedup vs baseline: 2.5500x; 2.5500x over previous
#include <cuda_runtime.h>
#include <cstdint>

#define PATCH 16
#define EMBED 384
#define IMG_HW 224
#define GRID_HW 14
#define NPATCH 196
#define M_TOTAL 12544
#define K_TOTAL 768
#define CHAN_STRIDE 50176
#define M_CTA 112
#define N_CTAS 112               // M_TOTAL / M_CTA

// tf32-rounded weights scratch (written every launch by wcvt_kernel)
__device__ uint32_t g_wtf32[EMBED * K_TOTAL];

// ---- dynamic smem layout (bytes) ----
#define A_STRIDE 144             // 36 floats per row (padded, 16B-aligned rows)
#define B_STRIDE 144
#define SM_A0    0
#define SM_A1    16128           // 112*144
#define SM_B0    32256
#define SM_B1    87552           // +384*144
#define SM_BIAS  142848
#define SM_GAMMA (SM_BIAS + 1536)
#define SM_BETA  (SM_GAMMA + 1536)
#define SM_RSUM  (SM_BETA + 1536)
#define SM_RSQ   (SM_RSUM + 512)
#define SM_MU    (SM_RSQ + 512)
#define SM_RS    (SM_MU + 512)
#define SMEM_TOTAL (SM_RS + 512) // 149504

__device__ __forceinline__ uint32_t smem_u32(const void* p) {
    uint32_t a;
    asm("{ .reg .u64 t; cvta.to.shared.u64 t, %1; cvt.u32.u64 %0, t; }"
        : "=r"(a) : "l"(p));
    return a;
}
__device__ __forceinline__ uint32_t f2tf32(float x) {
    uint32_t t;
    asm("cvt.rna.tf32.f32 %0, %1;" : "=r"(t) : "f"(x));
    return t;
}
__device__ __forceinline__ void cp16(uint32_t dst, const void* src) {
    asm volatile("cp.async.cg.shared.global [%0], [%1], 16;"
                 :: "r"(dst), "l"(src) : "memory");
}
#define CP_COMMIT() asm volatile("cp.async.commit_group;" ::: "memory")
#define CP_WAIT()   asm volatile("cp.async.wait_group 0;" ::: "memory")

// ---------------------------------------------------------------------------
// Entropy: warp per patch; conflict-free histogram via vcmpeq4/popc.
// ---------------------------------------------------------------------------
__global__ __launch_bounds__(256) void entropy_kernel(
    const float* __restrict__ img, float* __restrict__ ent) {
    __shared__ uint32_t qbuf[8][64];
    const int tid = threadIdx.x;
    const int wid = tid >> 5;
    const int lid = tid & 31;
    const int m = blockIdx.x * 8 + wid;

    const int b = m / NPATCH;
    const int pidx = m % NPATCH;
    const int gh = pidx / GRID_HW;
    const int gw = pidx % GRID_HW;
    const int prow = lid >> 1;
    const int pcol = (lid & 1) * 8;

    const size_t base = (size_t)(b * 3) * CHAN_STRIDE
                      + (size_t)(gh * PATCH + prow) * IMG_HW + (gw * PATCH + pcol);
    float4 a0 = *(const float4*)(img + base);
    float4 a1 = *(const float4*)(img + base + 4);
    float4 b0 = *(const float4*)(img + base + CHAN_STRIDE);
    float4 b1 = *(const float4*)(img + base + CHAN_STRIDE + 4);
    float4 c0 = *(const float4*)(img + base + 2 * CHAN_STRIDE);
    float4 c1 = *(const float4*)(img + base + 2 * CHAN_STRIDE + 4);

    float g[8];
    g[0] = (a0.x + b0.x + c0.x) / 3.0f;
    g[1] = (a0.y + b0.y + c0.y) / 3.0f;
    g[2] = (a0.z + b0.z + c0.z) / 3.0f;
    g[3] = (a0.w + b0.w + c0.w) / 3.0f;
    g[4] = (a1.x + b1.x + c1.x) / 3.0f;
    g[5] = (a1.y + b1.y + c1.y) / 3.0f;
    g[6] = (a1.z + b1.z + c1.z) / 3.0f;
    g[7] = (a1.w + b1.w + c1.w) / 3.0f;

    uint32_t q[8];
    #pragma unroll
    for (int i = 0; i < 8; i++)
        q[i] = (uint32_t)(int)fminf(fmaxf(g[i] * 31.0f, 0.0f), 31.0f);
    qbuf[wid][lid * 2]     = q[0] | (q[1] << 8) | (q[2] << 16) | (q[3] << 24);
    qbuf[wid][lid * 2 + 1] = q[4] | (q[5] << 8) | (q[6] << 16) | (q[7] << 24);
    __syncwarp();

    const uint32_t pat = 0x01010101u * (uint32_t)lid;
    int bits = 0;
    #pragma unroll
    for (int i = 0; i < 64; i++) bits += __popc(__vcmpeq4(qbuf[wid][i], pat));

    float p = (float)(bits >> 3) * (1.0f / 256.0f);
    float t = p * log2f(p + 1e-10f);
    #pragma unroll
    for (int o = 16; o; o >>= 1) t += __shfl_xor_sync(0xffffffffu, t, o);
    if (lid == 0) ent[m] = -t * 0.2f;
}

// ---------------------------------------------------------------------------
// Weight tf32 pre-round: w -> g_wtf32 (RNA). 294912 floats = 73728 float4.
// ---------------------------------------------------------------------------
__global__ __launch_bounds__(256) void wcvt_kernel(const float* __restrict__ w) {
    int i = blockIdx.x * 256 + threadIdx.x;
    float4 v = ((const float4*)w)[i];
    uint4 t = make_uint4(f2tf32(v.x), f2tf32(v.y), f2tf32(v.z), f2tf32(v.w));
    ((uint4*)g_wtf32)[i] = t;
}

// ---------------------------------------------------------------------------
// Fused patch-embed GEMM (mma.sync tf32) + bias + LayerNorm.
// CTA: 112 rows x full N=384. Warp w: all 7 m-tiles x 6 n-tiles (cols 48w..).
// ---------------------------------------------------------------------------
__global__ __launch_bounds__(256, 1) void gemm_ln_kernel(
    const float* __restrict__ img, const float* __restrict__ bias,
    const float* __restrict__ gamma, const float* __restrict__ beta,
    float* __restrict__ out) {
    extern __shared__ char smem[];
    const uint32_t sbase = smem_u32(smem);
    const int tid = threadIdx.x;
    const int wid = tid >> 5;
    const int lid = tid & 31;
    const int qr = lid >> 2;     // 0..7
    const int qc = lid & 3;      // 0..3
    const int bm = blockIdx.x;

    // Stage LN params.
    for (int i = tid; i < EMBED; i += 256) {
        ((float*)(smem + SM_BIAS))[i]  = bias[i];
        ((float*)(smem + SM_GAMMA))[i] = gamma[i];
        ((float*)(smem + SM_BETA))[i]  = beta[i];
    }

    // Per-thread A gather bases (rows fixed across chunks).
    const float* asrc[4];
    #pragma unroll
    for (int i = 0; i < 4; i++) {
        int u = tid + 256 * i;
        if (u < 896) {
            int row = u >> 3;
            int m = bm * M_CTA + row;
            int b = m / NPATCH;
            int pp = m % NPATCH;
            asrc[i] = img + (size_t)(b * 3) * CHAN_STRIDE
                    + (size_t)((pp / GRID_HW) * PATCH) * IMG_HW
                    + (pp % GRID_HW) * PATCH;
        } else asrc[i] = nullptr;
    }

    auto load_chunk = [&](int c, int pbuf) {
        const uint32_t Ad = sbase + (pbuf ? SM_A1 : SM_A0);
        const uint32_t Bd = sbase + (pbuf ? SM_B1 : SM_B0);
        #pragma unroll
        for (int i = 0; i < 4; i++) {
            int u = tid + 256 * i;
            if (u < 896) {
                int row = u >> 3, c4 = u & 7;
                int k = c * 32 + c4 * 4;
                int ch = k >> 8, pi = (k >> 4) & 15, pj = k & 15;
                cp16(Ad + row * A_STRIDE + c4 * 16,
                     asrc[i] + (size_t)ch * CHAN_STRIDE + pi * IMG_HW + pj);
            }
        }
        const uint32_t* wsrc = g_wtf32 + c * 32;
        #pragma unroll
        for (int i = 0; i < 12; i++) {
            int u = tid + 256 * i;
            int row = u >> 3, seg = u & 7;
            cp16(Bd + row * B_STRIDE + seg * 16,
                 wsrc + (size_t)row * K_TOTAL + seg * 4);
        }
        CP_COMMIT();
    };

    auto cvt_chunk = [&](int pbuf) {   // round A to tf32 (RNA) in place
        char* Ab = smem + (pbuf ? SM_A1 : SM_A0);
        #pragma unroll
        for (int i = 0; i < 4; i++) {
            int u = tid + 256 * i;
            if (u < 896) {
                float4* p4 = (float4*)(Ab + (u >> 3) * A_STRIDE + (u & 7) * 16);
                float4 v = *p4;
                *(uint4*)p4 = make_uint4(f2tf32(v.x), f2tf32(v.y),
                                         f2tf32(v.z), f2tf32(v.w));
            }
        }
    };

    float acc[168];
    #pragma unroll
    for (int i = 0; i < 168; i++) acc[i] = 0.0f;

    load_chunk(0, 0);
    CP_WAIT();
    __syncthreads();

    int p = 0;
    for (int c = 0; c < 24; c++) {
        cvt_chunk(p);
        if (c < 23) load_chunk(c + 1, p ^ 1);
        __syncthreads();   // cvt visible to all warps

        const char* Ab = smem + (p ? SM_A1 : SM_A0);
        const char* Bb = smem + (p ? SM_B1 : SM_B0);
        #pragma unroll
        for (int s = 0; s < 4; s++) {
            const int k0 = s * 8;
            uint32_t a[7][4];
            #pragma unroll
            for (int i = 0; i < 7; i++) {
                const uint32_t* ar =
                    (const uint32_t*)(Ab + (16 * i + qr) * A_STRIDE) + k0 + qc;
                const uint32_t* ar8 =
                    (const uint32_t*)(Ab + (16 * i + qr + 8) * A_STRIDE) + k0 + qc;
                a[i][0] = ar[0];  a[i][2] = ar[4];
                a[i][1] = ar8[0]; a[i][3] = ar8[4];
            }
            #pragma unroll
            for (int t = 0; t < 6; t++) {
                const uint32_t* br =
                    (const uint32_t*)(Bb + (48 * wid + 8 * t + qr) * B_STRIDE) + k0 + qc;
                uint32_t b0 = br[0], b1 = br[4];
                #pragma unroll
                for (int i = 0; i < 7; i++) {
                    float* d = acc + (i * 6 + t) * 4;
                    asm volatile(
                        "mma.sync.aligned.m16n8k8.row.col.f32.tf32.tf32.f32 "
                        "{%0,%1,%2,%3}, {%4,%5,%6,%7}, {%8,%9}, {%0,%1,%2,%3};"
                        : "+f"(d[0]), "+f"(d[1]), "+f"(d[2]), "+f"(d[3])
                        : "r"(a[i][0]), "r"(a[i][1]), "r"(a[i][2]), "r"(a[i][3]),
                          "r"(b0), "r"(b1));
                }
            }
        }
        if (c < 23) CP_WAIT();
        __syncthreads();
        p ^= 1;
    }

    // ---------------- fused LayerNorm epilogue ----------------
    float* rsum = (float*)(smem + SM_RSUM);
    float* rsq  = (float*)(smem + SM_RSQ);
    if (tid < M_CTA) { rsum[tid] = 0.0f; rsq[tid] = 0.0f; }
    __syncthreads();

    const float* sbias = (const float*)(smem + SM_BIAS);
    float2 bs2[6];
    #pragma unroll
    for (int t = 0; t < 6; t++)
        bs2[t] = *(const float2*)&sbias[48 * wid + 8 * t + 2 * qc];

    #pragma unroll
    for (int i = 0; i < 7; i++) {
        float s0 = 0, q0 = 0, s1 = 0, q1 = 0;
        #pragma unroll
        for (int t = 0; t < 6; t++) {
            float* d = acc + (i * 6 + t) * 4;
            d[0] += bs2[t].x; d[1] += bs2[t].y;
            d[2] += bs2[t].x; d[3] += bs2[t].y;
            s0 += d[0] + d[1]; q0 += d[0] * d[0] + d[1] * d[1];
            s1 += d[2] + d[3]; q1 += d[2] * d[2] + d[3] * d[3];
        }
        #pragma unroll
        for (int o = 1; o <= 2; o <<= 1) {
            s0 += __shfl_xor_sync(0xffffffffu, s0, o);
            q0 += __shfl_xor_sync(0xffffffffu, q0, o);
            s1 += __shfl_xor_sync(0xffffffffu, s1, o);
            q1 += __shfl_xor_sync(0xffffffffu, q1, o);
        }
        if (qc == 0) {
            atomicAdd(&rsum[16 * i + qr], s0);
            atomicAdd(&rsq[16 * i + qr], q0);
            atomicAdd(&rsum[16 * i + qr + 8], s1);
            atomicAdd(&rsq[16 * i + qr + 8], q1);
        }
    }
    __syncthreads();

    float* smu = (float*)(smem + SM_MU);
    float* srs = (float*)(smem + SM_RS);
    if (tid < M_CTA) {
        float mu = rsum[tid] * (1.0f / EMBED);
        float vv = rsq[tid] * (1.0f / EMBED) - mu * mu;
        smu[tid] = mu;
        srs[tid] = rsqrtf(fmaxf(vv, 0.0f) + 1e-5f);
    }
    __syncthreads();

    const float* sg = (const float*)(smem + SM_GAMMA);
    const float* sb = (const float*)(smem + SM_BETA);
    float2 g2[6], be2[6];
    #pragma unroll
    for (int t = 0; t < 6; t++) {
        g2[t]  = *(const float2*)&sg[48 * wid + 8 * t + 2 * qc];
        be2[t] = *(const float2*)&sb[48 * wid + 8 * t + 2 * qc];
    }

    #pragma unroll
    for (int i = 0; i < 7; i++) {
        const int r0 = 16 * i + qr;
        const float mu0 = smu[r0], rs0 = srs[r0];
        const float mu1 = smu[r0 + 8], rs1 = srs[r0 + 8];
        float* o0 = out + (size_t)(bm * M_CTA + r0) * EMBED + 48 * wid + 2 * qc;
        float* o1 = o0 + 8 * (size_t)EMBED;
        #pragma unroll
        for (int t = 0; t < 6; t++) {
            float* d = acc + (i * 6 + t) * 4;
            float2 v0, v1;
            v0.x = (d[0] - mu0) * rs0 * g2[t].x + be2[t].x;
            v0.y = (d[1] - mu0) * rs0 * g2[t].y + be2[t].y;
            v1.x = (d[2] - mu1) * rs1 * g2[t].x + be2[t].x;
            v1.y = (d[3] - mu1) * rs1 * g2[t].y + be2[t].y;
            *(float2*)(o0 + 8 * t) = v0;
            *(float2*)(o1 + 8 * t) = v1;
        }
    }
}

// ---------------------------------------------------------------------------
extern "C" void kernel_launch(void* const* d_in, const int* in_sizes, int n_in,
                              void* d_out, int out_size) {
    const float* images = (const float*)d_in[0];
    const float* proj_w = (const float*)d_in[1];
    const float* proj_b = (const float*)d_in[2];
    const float* ln_g   = (const float*)d_in[3];
    const float* ln_b   = (const float*)d_in[4];
    float* out = (float*)d_out;

    float* x   = out;
    float* ent = out + (size_t)M_TOTAL * EMBED;

    cudaFuncSetAttribute(gemm_ln_kernel,
                         cudaFuncAttributeMaxDynamicSharedMemorySize, SMEM_TOTAL);

    wcvt_kernel<<<(EMBED * K_TOTAL) / 1024, 256>>>(proj_w);
    entropy_kernel<<<M_TOTAL / 8, 256>>>(images, ent);
    gemm_ln_kernel<<<N_CTAS, 256, SMEM_TOTAL>>>(images, proj_b, ln_g, ln_b, x);
}

// round 6
// speedup vs baseline: 4.4860x; 1.7592x over previous
#include <cuda_runtime.h>
#include <cuda_fp16.h>
#include <cstdint>

#define PATCH 16
#define EMBED 384
#define IMG_HW 224
#define GRID_HW 14
#define NPATCH 196
#define M_TOTAL 12544
#define K_TOTAL 768
#define CHAN_STRIDE 50176
#define M_CTA 112
#define N_CTAS 112
#define NCHUNK 24            // K chunks of 32

// W pre-converted to fp16, chunk-major, ldmatrix-swizzled:
// halfs offset = c*12288 + n*32 + (seg ^ ((n>>1)&3))*8 + (k&7)
__device__ __half g_wh[NCHUNK * EMBED * 32];

// ---- dynamic smem layout (bytes) ----
#define B_BUF_BYTES 24576        // 384 rows x 64B
#define A_STRIDE 80              // 32 halfs (64B) + 16B pad
#define A_BUF_BYTES (M_CTA * A_STRIDE)   // 8960
#define SM_B0    0               // 3 buffers
#define SM_A0    73728           // 2 buffers
#define SM_BIAS  91648
#define SM_GAMMA 93184
#define SM_BETA  94720
#define SM_RSUM  96256
#define SM_RSQ   96768
#define SM_MU    97280
#define SM_RS    97792
#define SM_MBAR  98304           // 3 x 8B
#define SMEM_TOTAL 98432

__device__ __forceinline__ uint32_t smem_u32(const void* p) {
    uint32_t a;
    asm("{ .reg .u64 t; cvta.to.shared.u64 t, %1; cvt.u32.u64 %0, t; }"
        : "=r"(a) : "l"(p));
    return a;
}
__device__ __forceinline__ uint32_t pack2(float a, float b) {
    __half2 h = __floats2half2_rn(a, b);
    return *reinterpret_cast<uint32_t*>(&h);
}

#define MBAR_INIT(addr, cnt) \
    asm volatile("mbarrier.init.shared.b64 [%0], %1;" :: "r"(addr), "r"(cnt) : "memory")
#define MBAR_EXPECT_TX(addr, bytes) \
    asm volatile("mbarrier.arrive.expect_tx.shared.b64 _, [%0], %1;" \
                 :: "r"(addr), "r"(bytes) : "memory")
#define BULK_CP(dst, src, bytes, mbar) \
    asm volatile("cp.async.bulk.shared::cta.global.mbarrier::complete_tx::bytes " \
                 "[%0], [%1], %2, [%3];" \
                 :: "r"(dst), "l"(src), "r"(bytes), "r"(mbar) : "memory")
#define MBAR_WAIT(addr, par) do {                                              \
    uint32_t _m = (addr); uint32_t _p = (par); uint32_t _d;                    \
    asm volatile("{\n\t.reg .pred p;\n\t"                                      \
        "mbarrier.try_wait.parity.acquire.cta.shared::cta.b64 p, [%1], %2;\n\t"\
        "selp.b32 %0, 1, 0, p;\n\t}"                                           \
        : "=r"(_d) : "r"(_m), "r"(_p) : "memory");                             \
    if (!_d) {                                                                 \
        asm volatile("{\n\t.reg .pred P1;\n\t"                                 \
            "W%=:\n\t"                                                         \
            "mbarrier.try_wait.parity.acquire.cta.shared::cta.b64 P1, [%0], %1, 0x989680;\n\t" \
            "@P1 bra.uni D%=;\n\t"                                             \
            "bra.uni W%=;\n\t"                                                 \
            "D%=:\n\t}" :: "r"(_m), "r"(_p) : "memory");                       \
    }                                                                          \
} while (0)

#define LDSM4(r0, r1, r2, r3, a) \
    asm volatile("ldmatrix.sync.aligned.m8n8.x4.shared.b16 {%0,%1,%2,%3}, [%4];" \
                 : "=r"(r0), "=r"(r1), "=r"(r2), "=r"(r3) : "r"(a))

#define MMA16816(d, a, b0, b1) \
    asm volatile("mma.sync.aligned.m16n8k16.row.col.f32.f16.f16.f32 " \
                 "{%0,%1,%2,%3}, {%4,%5,%6,%7}, {%8,%9}, {%0,%1,%2,%3};" \
                 : "+f"((d)[0]), "+f"((d)[1]), "+f"((d)[2]), "+f"((d)[3]) \
                 : "r"((a)[0]), "r"((a)[1]), "r"((a)[2]), "r"((a)[3]), \
                   "r"(b0), "r"(b1))

// ---------------------------------------------------------------------------
// prep kernel: blocks [0,1568) entropy (warp/patch), [1568,1856) W fp16 cvt.
// ---------------------------------------------------------------------------
__global__ __launch_bounds__(256) void prep_kernel(
    const float* __restrict__ img, const float* __restrict__ w,
    float* __restrict__ ent) {
    const int tid = threadIdx.x;
    if (blockIdx.x >= 1568) {
        // W convert: 73728 float4s over 288 blocks.
        int i = (blockIdx.x - 1568) * 256 + tid;
        int n = i / 192;
        int k = (i % 192) * 4;
        float4 v = *(const float4*)(w + (size_t)n * K_TOTAL + k);
        int c = k >> 5;
        int kin = k & 31;
        int seg = kin >> 3;
        int phys = seg ^ ((n >> 1) & 3);
        uint32_t* dst = (uint32_t*)(g_wh + c * 12288 + n * 32 + phys * 8 + (kin & 7));
        dst[0] = pack2(v.x, v.y);
        dst[1] = pack2(v.z, v.w);
        return;
    }

    __shared__ uint32_t qbuf[8][64];
    const int wid = tid >> 5;
    const int lid = tid & 31;
    const int m = blockIdx.x * 8 + wid;
    const int b = m / NPATCH;
    const int pidx = m % NPATCH;
    const int gh = pidx / GRID_HW;
    const int gw = pidx % GRID_HW;
    const int prow = lid >> 1;
    const int pcol = (lid & 1) * 8;

    const size_t base = (size_t)(b * 3) * CHAN_STRIDE
                      + (size_t)(gh * PATCH + prow) * IMG_HW + (gw * PATCH + pcol);
    float4 a0 = *(const float4*)(img + base);
    float4 a1 = *(const float4*)(img + base + 4);
    float4 b0 = *(const float4*)(img + base + CHAN_STRIDE);
    float4 b1 = *(const float4*)(img + base + CHAN_STRIDE + 4);
    float4 c0 = *(const float4*)(img + base + 2 * CHAN_STRIDE);
    float4 c1 = *(const float4*)(img + base + 2 * CHAN_STRIDE + 4);

    float g[8];
    g[0] = (a0.x + b0.x + c0.x) / 3.0f;
    g[1] = (a0.y + b0.y + c0.y) / 3.0f;
    g[2] = (a0.z + b0.z + c0.z) / 3.0f;
    g[3] = (a0.w + b0.w + c0.w) / 3.0f;
    g[4] = (a1.x + b1.x + c1.x) / 3.0f;
    g[5] = (a1.y + b1.y + c1.y) / 3.0f;
    g[6] = (a1.z + b1.z + c1.z) / 3.0f;
    g[7] = (a1.w + b1.w + c1.w) / 3.0f;

    uint32_t q[8];
    #pragma unroll
    for (int i = 0; i < 8; i++)
        q[i] = (uint32_t)(int)fminf(fmaxf(g[i] * 31.0f, 0.0f), 31.0f);
    qbuf[wid][lid * 2]     = q[0] | (q[1] << 8) | (q[2] << 16) | (q[3] << 24);
    qbuf[wid][lid * 2 + 1] = q[4] | (q[5] << 8) | (q[6] << 16) | (q[7] << 24);
    __syncwarp();

    const uint32_t pat = 0x01010101u * (uint32_t)lid;
    int bits = 0;
    #pragma unroll
    for (int i = 0; i < 64; i++) bits += __popc(__vcmpeq4(qbuf[wid][i], pat));

    float p = (float)(bits >> 3) * (1.0f / 256.0f);
    float t = p * log2f(p + 1e-10f);
    #pragma unroll
    for (int o = 16; o; o >>= 1) t += __shfl_xor_sync(0xffffffffu, t, o);
    if (lid == 0) ent[m] = -t * 0.2f;
}

// ---------------------------------------------------------------------------
// Fused GEMM (fp16 mma.m16n8k16) + bias + LayerNorm.
// CTA = 112 rows x 384 cols. B via cp.async.bulk (3-stage), A gathered+cvt.
// ---------------------------------------------------------------------------
__global__ __launch_bounds__(256) void gemm_ln_kernel(
    const float* __restrict__ img, const float* __restrict__ bias,
    const float* __restrict__ gamma, const float* __restrict__ beta,
    float* __restrict__ out) {
    extern __shared__ char smem[];
    const uint32_t sbase = smem_u32(smem);
    const int tid = threadIdx.x;
    const int wid = tid >> 5;
    const int lid = tid & 31;
    const int qr = lid >> 2;
    const int qc = lid & 3;
    const int bm = blockIdx.x;

    for (int i = tid; i < EMBED; i += 256) {
        ((float*)(smem + SM_BIAS))[i]  = bias[i];
        ((float*)(smem + SM_GAMMA))[i] = gamma[i];
        ((float*)(smem + SM_BETA))[i]  = beta[i];
    }
    if (tid == 0) {
        MBAR_INIT(sbase + SM_MBAR + 0, 1);
        MBAR_INIT(sbase + SM_MBAR + 8, 1);
        MBAR_INIT(sbase + SM_MBAR + 16, 1);
        #pragma unroll
        for (int s = 0; s < 3; s++) {
            MBAR_EXPECT_TX(sbase + SM_MBAR + 8 * s, B_BUF_BYTES);
            BULK_CP(sbase + SM_B0 + s * B_BUF_BYTES,
                    (const char*)g_wh + s * B_BUF_BYTES, B_BUF_BYTES,
                    sbase + SM_MBAR + 8 * s);
        }
    }

    // A gather geometry: units u = tid, tid+256 (u<448): row=u>>2, seg=u&3.
    const float* aptr[2];
    {
        int r = tid >> 2;
        int m = bm * M_CTA + r;
        aptr[0] = img + (size_t)((m / NPATCH) * 3) * CHAN_STRIDE
                + (size_t)(((m % NPATCH) / GRID_HW) * PATCH) * IMG_HW
                + ((m % NPATCH) % GRID_HW) * PATCH;
        if (tid < 192) {
            int m2 = bm * M_CTA + r + 64;
            aptr[1] = img + (size_t)((m2 / NPATCH) * 3) * CHAN_STRIDE
                    + (size_t)(((m2 % NPATCH) / GRID_HW) * PATCH) * IMG_HW
                    + ((m2 % NPATCH) % GRID_HW) * PATCH;
        } else aptr[1] = nullptr;
    }
    const int seg = tid & 3;
    const int arow0 = tid >> 2;

    auto a_offset = [&](int c) -> size_t {
        int k = c * 32 + seg * 8;
        return (size_t)(k >> 8) * CHAN_STRIDE + ((k >> 4) & 15) * IMG_HW + (k & 15);
    };
    auto a_store = [&](int pbuf, float4 v0, float4 v1, float4 v2, float4 v3) {
        char* Ab = smem + SM_A0 + pbuf * A_BUF_BYTES;
        uint4 s0 = make_uint4(pack2(v0.x, v0.y), pack2(v0.z, v0.w),
                              pack2(v1.x, v1.y), pack2(v1.z, v1.w));
        *(uint4*)(Ab + arow0 * A_STRIDE + seg * 16) = s0;
        if (tid < 192) {
            uint4 s1 = make_uint4(pack2(v2.x, v2.y), pack2(v2.z, v2.w),
                                  pack2(v3.x, v3.y), pack2(v3.z, v3.w));
            *(uint4*)(Ab + (arow0 + 64) * A_STRIDE + seg * 16) = s1;
        }
    };

    // Prologue: A chunk 0.
    {
        size_t o = a_offset(0);
        float4 v0 = *(const float4*)(aptr[0] + o);
        float4 v1 = *(const float4*)(aptr[0] + o + 4);
        float4 v2 = make_float4(0, 0, 0, 0), v3 = v2;
        if (tid < 192) {
            v2 = *(const float4*)(aptr[1] + o);
            v3 = *(const float4*)(aptr[1] + o + 4);
        }
        a_store(0, v0, v1, v2, v3);
    }
    __syncthreads();

    float acc[168];
    #pragma unroll
    for (int i = 0; i < 168; i++) acc[i] = 0.0f;

    // ldmatrix lane-address components.
    const int a_rowoff = ((lid >> 3) & 1) * 8 + (lid & 7);   // within m-tile
    const int a_hi = (lid >> 4) * 16;
    const int b_noff = ((lid >> 4) & 1) * 8 + (lid & 7);     // tile-pair row
    const int b_segbit = (lid >> 3) & 1;                     // seg low bit
    const int b_xr = ((lid & 7) >> 1) & 3;                   // swizzle xor

    for (int c = 0; c < NCHUNK; c++) {
        const int pB = c % 3;
        const int pA = c & 1;
        MBAR_WAIT(sbase + SM_MBAR + 8 * pB, (c / 3) & 1);

        // Prefetch A chunk c+1.
        float4 v0, v1, v2, v3;
        if (c < NCHUNK - 1) {
            size_t o = a_offset(c + 1);
            v0 = *(const float4*)(aptr[0] + o);
            v1 = *(const float4*)(aptr[0] + o + 4);
            if (tid < 192) {
                v2 = *(const float4*)(aptr[1] + o);
                v3 = *(const float4*)(aptr[1] + o + 4);
            }
        }

        const uint32_t Abase = sbase + SM_A0 + pA * A_BUF_BYTES;
        const uint32_t Bbase = sbase + SM_B0 + pB * B_BUF_BYTES;
        #pragma unroll
        for (int s = 0; s < 2; s++) {
            uint32_t a[7][4];
            #pragma unroll
            for (int i = 0; i < 7; i++) {
                uint32_t ad = Abase + (16 * i + a_rowoff) * A_STRIDE + s * 32 + a_hi;
                LDSM4(a[i][0], a[i][1], a[i][2], a[i][3], ad);
            }
            #pragma unroll
            for (int tp = 0; tp < 3; tp++) {
                int n = 48 * wid + 16 * tp + b_noff;
                int sg = (2 * s + b_segbit) ^ b_xr;
                uint32_t bd = Bbase + n * 64 + sg * 16;
                uint32_t b0, b1, b2, b3;
                LDSM4(b0, b1, b2, b3, bd);
                #pragma unroll
                for (int i = 0; i < 7; i++) {
                    MMA16816(acc + (i * 6 + 2 * tp) * 4, a[i], b0, b1);
                    MMA16816(acc + (i * 6 + 2 * tp + 1) * 4, a[i], b2, b3);
                }
            }
        }

        if (c < NCHUNK - 1) a_store(pA ^ 1, v0, v1, v2, v3);
        __syncthreads();
        if (tid == 0 && c + 3 < NCHUNK) {
            MBAR_EXPECT_TX(sbase + SM_MBAR + 8 * pB, B_BUF_BYTES);
            BULK_CP(sbase + SM_B0 + pB * B_BUF_BYTES,
                    (const char*)g_wh + (size_t)(c + 3) * B_BUF_BYTES,
                    B_BUF_BYTES, sbase + SM_MBAR + 8 * pB);
        }
    }

    // ---------------- fused LayerNorm epilogue ----------------
    float* rsum = (float*)(smem + SM_RSUM);
    float* rsq  = (float*)(smem + SM_RSQ);
    if (tid < M_CTA) { rsum[tid] = 0.0f; rsq[tid] = 0.0f; }
    __syncthreads();

    const float* sbias = (const float*)(smem + SM_BIAS);
    float2 bs2[6];
    #pragma unroll
    for (int t = 0; t < 6; t++)
        bs2[t] = *(const float2*)&sbias[48 * wid + 8 * t + 2 * qc];

    #pragma unroll
    for (int i = 0; i < 7; i++) {
        float s0 = 0, q0 = 0, s1 = 0, q1 = 0;
        #pragma unroll
        for (int t = 0; t < 6; t++) {
            float* d = acc + (i * 6 + t) * 4;
            d[0] += bs2[t].x; d[1] += bs2[t].y;
            d[2] += bs2[t].x; d[3] += bs2[t].y;
            s0 += d[0] + d[1]; q0 += d[0] * d[0] + d[1] * d[1];
            s1 += d[2] + d[3]; q1 += d[2] * d[2] + d[3] * d[3];
        }
        #pragma unroll
        for (int o = 1; o <= 2; o <<= 1) {
            s0 += __shfl_xor_sync(0xffffffffu, s0, o);
            q0 += __shfl_xor_sync(0xffffffffu, q0, o);
            s1 += __shfl_xor_sync(0xffffffffu, s1, o);
            q1 += __shfl_xor_sync(0xffffffffu, q1, o);
        }
        if (qc == 0) {
            atomicAdd(&rsum[16 * i + qr], s0);
            atomicAdd(&rsq[16 * i + qr], q0);
            atomicAdd(&rsum[16 * i + qr + 8], s1);
            atomicAdd(&rsq[16 * i + qr + 8], q1);
        }
    }
    __syncthreads();

    float* smu = (float*)(smem + SM_MU);
    float* srs = (float*)(smem + SM_RS);
    if (tid < M_CTA) {
        float mu = rsum[tid] * (1.0f / EMBED);
        float vv = rsq[tid] * (1.0f / EMBED) - mu * mu;
        smu[tid] = mu;
        srs[tid] = rsqrtf(fmaxf(vv, 0.0f) + 1e-5f);
    }
    __syncthreads();

    const float* sg = (const float*)(smem + SM_GAMMA);
    const float* sb = (const float*)(smem + SM_BETA);
    float2 g2[6], be2[6];
    #pragma unroll
    for (int t = 0; t < 6; t++) {
        g2[t]  = *(const float2*)&sg[48 * wid + 8 * t + 2 * qc];
        be2[t] = *(const float2*)&sb[48 * wid + 8 * t + 2 * qc];
    }

    #pragma unroll
    for (int i = 0; i < 7; i++) {
        const int r0 = 16 * i + qr;
        const float mu0 = smu[r0], rs0 = srs[r0];
        const float mu1 = smu[r0 + 8], rs1 = srs[r0 + 8];
        float* o0 = out + (size_t)(bm * M_CTA + r0) * EMBED + 48 * wid + 2 * qc;
        float* o1 = o0 + 8 * (size_t)EMBED;
        #pragma unroll
        for (int t = 0; t < 6; t++) {
            float* d = acc + (i * 6 + t) * 4;
            float2 w0, w1;
            w0.x = (d[0] - mu0) * rs0 * g2[t].x + be2[t].x;
            w0.y = (d[1] - mu0) * rs0 * g2[t].y + be2[t].y;
            w1.x = (d[2] - mu1) * rs1 * g2[t].x + be2[t].x;
            w1.y = (d[3] - mu1) * rs1 * g2[t].y + be2[t].y;
            *(float2*)(o0 + 8 * t) = w0;
            *(float2*)(o1 + 8 * t) = w1;
        }
    }
}

// ---------------------------------------------------------------------------
extern "C" void kernel_launch(void* const* d_in, const int* in_sizes, int n_in,
                              void* d_out, int out_size) {
    const float* images = (const float*)d_in[0];
    const float* proj_w = (const float*)d_in[1];
    const float* proj_b = (const float*)d_in[2];
    const float* ln_g   = (const float*)d_in[3];
    const float* ln_b   = (const float*)d_in[4];
    float* out = (float*)d_out;

    float* x   = out;
    float* ent = out + (size_t)M_TOTAL * EMBED;

    cudaFuncSetAttribute(gemm_ln_kernel,
                         cudaFuncAttributeMaxDynamicSharedMemorySize, SMEM_TOTAL);

    prep_kernel<<<1568 + 288, 256>>>(images, proj_w, ent);
    gemm_ln_kernel<<<N_CTAS, 256, SMEM_TOTAL>>>(images, proj_b, ln_g, ln_b, x);
}

// round 7
// speedup vs baseline: 4.4977x; 1.0026x over previous
#include <cuda_runtime.h>
#include <cuda_fp16.h>
#include <cstdint>

#define PATCH 16
#define EMBED 384
#define IMG_HW 224
#define GRID_HW 14
#define NPATCH 196
#define M_TOTAL 12544
#define K_TOTAL 768
#define CHAN_STRIDE 50176
#define M_CTA 112
#define N_CTAS 112
#define NCHUNK 24
#define NSTAGE 4

// B: fp16, chunk-major, ldmatrix-swizzled: halfs c*12288 + n*32 + (seg^((n>>1)&3))*8 + k7
__device__ __half g_wh[NCHUNK * EMBED * 32];
// A: fp16, chunk-major: halfs c*(M_TOTAL*32) + m*32 + (seg^((m>>1)&3))*8 + k7
__device__ __half g_ah[(size_t)NCHUNK * M_TOTAL * 32];

#define A_SLAB_BYTES (M_TOTAL * 64)      // 802816 per chunk
#define B_CH_BYTES   24576               // 384*64
#define A_CTA_BYTES  7168                // 112*64
#define STAGE_BYTES  (B_CH_BYTES + A_CTA_BYTES)   // 31744

// ---- dynamic smem (bytes) ----
#define SM_BIAS  (NSTAGE * STAGE_BYTES)  // 126976
#define SM_GAMMA (SM_BIAS + 1536)
#define SM_BETA  (SM_GAMMA + 1536)
#define SM_RSUM  (SM_BETA + 1536)
#define SM_RSQ   (SM_RSUM + 512)
#define SM_MU    (SM_RSQ + 512)
#define SM_RS    (SM_MU + 512)
#define SM_MBAR  (SM_RS + 512)           // 4 x 8B
#define SMEM_TOTAL (SM_MBAR + 64)        // 133696

__device__ __forceinline__ uint32_t smem_u32(const void* p) {
    uint32_t a;
    asm("{ .reg .u64 t; cvta.to.shared.u64 t, %1; cvt.u32.u64 %0, t; }"
        : "=r"(a) : "l"(p));
    return a;
}
__device__ __forceinline__ uint32_t pack2(float a, float b) {
    __half2 h = __floats2half2_rn(a, b);
    return *reinterpret_cast<uint32_t*>(&h);
}

#define MBAR_INIT(addr, cnt) \
    asm volatile("mbarrier.init.shared.b64 [%0], %1;" :: "r"(addr), "r"(cnt) : "memory")
#define MBAR_EXPECT_TX(addr, bytes) \
    asm volatile("mbarrier.arrive.expect_tx.shared.b64 _, [%0], %1;" \
                 :: "r"(addr), "r"(bytes) : "memory")
#define BULK_CP(dst, src, bytes, mbar) \
    asm volatile("cp.async.bulk.shared::cta.global.mbarrier::complete_tx::bytes " \
                 "[%0], [%1], %2, [%3];" \
                 :: "r"(dst), "l"(src), "r"(bytes), "r"(mbar) : "memory")
#define MBAR_WAIT(addr, par) do {                                              \
    uint32_t _m = (addr); uint32_t _p = (par); uint32_t _d;                    \
    asm volatile("{\n\t.reg .pred p;\n\t"                                      \
        "mbarrier.try_wait.parity.acquire.cta.shared::cta.b64 p, [%1], %2;\n\t"\
        "selp.b32 %0, 1, 0, p;\n\t}"                                           \
        : "=r"(_d) : "r"(_m), "r"(_p) : "memory");                             \
    if (!_d) {                                                                 \
        asm volatile("{\n\t.reg .pred P1;\n\t"                                 \
            "W%=:\n\t"                                                         \
            "mbarrier.try_wait.parity.acquire.cta.shared::cta.b64 P1, [%0], %1, 0x989680;\n\t" \
            "@P1 bra.uni D%=;\n\t"                                             \
            "bra.uni W%=;\n\t"                                                 \
            "D%=:\n\t}" :: "r"(_m), "r"(_p) : "memory");                       \
    }                                                                          \
} while (0)

#define LDSM4(r0, r1, r2, r3, a) \
    asm volatile("ldmatrix.sync.aligned.m8n8.x4.shared.b16 {%0,%1,%2,%3}, [%4];" \
                 : "=r"(r0), "=r"(r1), "=r"(r2), "=r"(r3) : "r"(a))

#define MMA16816(d, a0, a1, a2, a3, b0, b1) \
    asm volatile("mma.sync.aligned.m16n8k16.row.col.f32.f16.f16.f32 " \
                 "{%0,%1,%2,%3}, {%4,%5,%6,%7}, {%8,%9}, {%0,%1,%2,%3};" \
                 : "+f"((d)[0]), "+f"((d)[1]), "+f"((d)[2]), "+f"((d)[3]) \
                 : "r"(a0), "r"(a1), "r"(a2), "r"(a3), "r"(b0), "r"(b1))

// ---------------------------------------------------------------------------
// prep: blocks [0,1568) entropy + A fp16 convert (warp/patch);
//       blocks [1568,1856) W fp16 convert.
// ---------------------------------------------------------------------------
__global__ __launch_bounds__(256) void prep_kernel(
    const float* __restrict__ img, const float* __restrict__ w,
    float* __restrict__ ent) {
    const int tid = threadIdx.x;
    if (blockIdx.x >= 1568) {
        int i = (blockIdx.x - 1568) * 256 + tid;
        int n = i / 192;
        int k = (i % 192) * 4;
        float4 v = *(const float4*)(w + (size_t)n * K_TOTAL + k);
        int c = k >> 5;
        int kin = k & 31;
        int phys = (kin >> 3) ^ ((n >> 1) & 3);
        uint32_t* dst = (uint32_t*)(g_wh + c * 12288 + n * 32 + phys * 8 + (kin & 7));
        dst[0] = pack2(v.x, v.y);
        dst[1] = pack2(v.z, v.w);
        return;
    }

    __shared__ uint32_t qbuf[8][64];
    const int wid = tid >> 5;
    const int lid = tid & 31;
    const int m = blockIdx.x * 8 + wid;
    const int b = m / NPATCH;
    const int pidx = m % NPATCH;
    const int gh = pidx / GRID_HW;
    const int gw = pidx % GRID_HW;
    const int prow = lid >> 1;
    const int pcol = (lid & 1) * 8;

    const size_t base = (size_t)(b * 3) * CHAN_STRIDE
                      + (size_t)(gh * PATCH + prow) * IMG_HW + (gw * PATCH + pcol);
    float4 a0 = *(const float4*)(img + base);
    float4 a1 = *(const float4*)(img + base + 4);
    float4 b0 = *(const float4*)(img + base + CHAN_STRIDE);
    float4 b1 = *(const float4*)(img + base + CHAN_STRIDE + 4);
    float4 c0 = *(const float4*)(img + base + 2 * CHAN_STRIDE);
    float4 c1 = *(const float4*)(img + base + 2 * CHAN_STRIDE + 4);

    // A fp16 rows (chunk-major, swizzled).
    const int mswz = (m >> 1) & 3;
    const int kbase = prow * 16 + pcol;     // within-channel k
    #pragma unroll
    for (int ch = 0; ch < 3; ch++) {
        float4 lo = ch == 0 ? a0 : (ch == 1 ? b0 : c0);
        float4 hi = ch == 0 ? a1 : (ch == 1 ? b1 : c1);
        int k = ch * 256 + kbase;
        int c = k >> 5;
        int segp = ((k & 31) >> 3) ^ mswz;
        uint4* dst = (uint4*)(g_ah + (size_t)c * (M_TOTAL * 32) + m * 32 + segp * 8);
        *dst = make_uint4(pack2(lo.x, lo.y), pack2(lo.z, lo.w),
                          pack2(hi.x, hi.y), pack2(hi.z, hi.w));
    }

    float g[8];
    g[0] = (a0.x + b0.x + c0.x) / 3.0f;
    g[1] = (a0.y + b0.y + c0.y) / 3.0f;
    g[2] = (a0.z + b0.z + c0.z) / 3.0f;
    g[3] = (a0.w + b0.w + c0.w) / 3.0f;
    g[4] = (a1.x + b1.x + c1.x) / 3.0f;
    g[5] = (a1.y + b1.y + c1.y) / 3.0f;
    g[6] = (a1.z + b1.z + c1.z) / 3.0f;
    g[7] = (a1.w + b1.w + c1.w) / 3.0f;

    uint32_t q[8];
    #pragma unroll
    for (int i = 0; i < 8; i++)
        q[i] = (uint32_t)(int)fminf(fmaxf(g[i] * 31.0f, 0.0f), 31.0f);
    qbuf[wid][lid * 2]     = q[0] | (q[1] << 8) | (q[2] << 16) | (q[3] << 24);
    qbuf[wid][lid * 2 + 1] = q[4] | (q[5] << 8) | (q[6] << 16) | (q[7] << 24);
    __syncwarp();

    const uint32_t pat = 0x01010101u * (uint32_t)lid;
    int bits = 0;
    #pragma unroll
    for (int i = 0; i < 64; i++) bits += __popc(__vcmpeq4(qbuf[wid][i], pat));

    float p = (float)(bits >> 3) * (1.0f / 256.0f);
    float t = p * log2f(p + 1e-10f);
    #pragma unroll
    for (int o = 16; o; o >>= 1) t += __shfl_xor_sync(0xffffffffu, t, o);
    if (lid == 0) ent[m] = -t * 0.2f;
}

// ---------------------------------------------------------------------------
// GEMM (fp16 mma) + bias + LN. 384 threads / 12 warps; warp = 112 rows x 32 cols.
// A and B both arrive via cp.async.bulk into a 4-stage ring. No LDG in mainloop.
// ---------------------------------------------------------------------------
__global__ __launch_bounds__(384) void gemm_ln_kernel(
    const float* __restrict__ bias, const float* __restrict__ gamma,
    const float* __restrict__ beta, float* __restrict__ out) {
    extern __shared__ char smem[];
    const uint32_t sbase = smem_u32(smem);
    const int tid = threadIdx.x;
    const int wid = tid >> 5;
    const int lid = tid & 31;
    const int qr = lid >> 2;
    const int qc = lid & 3;
    const int bm = blockIdx.x;

    if (tid < EMBED) {
        ((float*)(smem + SM_BIAS))[tid]  = bias[tid];
        ((float*)(smem + SM_GAMMA))[tid] = gamma[tid];
        ((float*)(smem + SM_BETA))[tid]  = beta[tid];
    }
    if (tid < M_CTA) {
        ((float*)(smem + SM_RSUM))[tid] = 0.0f;
        ((float*)(smem + SM_RSQ))[tid]  = 0.0f;
    }
    if (tid == 0) {
        #pragma unroll
        for (int s = 0; s < NSTAGE; s++) {
            MBAR_INIT(sbase + SM_MBAR + 8 * s, 1);
            MBAR_EXPECT_TX(sbase + SM_MBAR + 8 * s, STAGE_BYTES);
            BULK_CP(sbase + s * STAGE_BYTES,
                    (const char*)g_wh + (size_t)s * B_CH_BYTES, B_CH_BYTES,
                    sbase + SM_MBAR + 8 * s);
            BULK_CP(sbase + s * STAGE_BYTES + B_CH_BYTES,
                    (const char*)g_ah + (size_t)s * A_SLAB_BYTES + bm * A_CTA_BYTES,
                    A_CTA_BYTES, sbase + SM_MBAR + 8 * s);
        }
    }
    __syncthreads();

    float acc[112];
    #pragma unroll
    for (int i = 0; i < 112; i++) acc[i] = 0.0f;

    // lane geometry
    const int a_row = ((lid >> 3) & 1) * 8 + (lid & 7);
    const int a_kbit = lid >> 4;
    const int b_noff = ((lid >> 4) & 1) * 8 + (lid & 7);
    const int b_segbit = (lid >> 3) & 1;
    const int xr = (lid & 7) >> 1;

    for (int c = 0; c < NCHUNK; c++) {
        const int s = c & (NSTAGE - 1);
        MBAR_WAIT(sbase + SM_MBAR + 8 * s, (c >> 2) & 1);

        const uint32_t Bst = sbase + s * STAGE_BYTES;
        const uint32_t Ast = Bst + B_CH_BYTES;
        #pragma unroll
        for (int sh = 0; sh < 2; sh++) {
            uint32_t bf[2][4];
            #pragma unroll
            for (int tp = 0; tp < 2; tp++) {
                int n = 32 * wid + 16 * tp + b_noff;
                int sg = (2 * sh + b_segbit) ^ xr;
                LDSM4(bf[tp][0], bf[tp][1], bf[tp][2], bf[tp][3],
                      Bst + n * 64 + sg * 16);
            }
            #pragma unroll
            for (int i = 0; i < 7; i++) {
                int r = 16 * i + a_row;
                int aseg = (2 * sh + a_kbit) ^ xr;
                uint32_t a0, a1, a2, a3;
                LDSM4(a0, a1, a2, a3, Ast + r * 64 + aseg * 16);
                MMA16816(acc + (i * 4 + 0) * 4, a0, a1, a2, a3, bf[0][0], bf[0][1]);
                MMA16816(acc + (i * 4 + 1) * 4, a0, a1, a2, a3, bf[0][2], bf[0][3]);
                MMA16816(acc + (i * 4 + 2) * 4, a0, a1, a2, a3, bf[1][0], bf[1][1]);
                MMA16816(acc + (i * 4 + 3) * 4, a0, a1, a2, a3, bf[1][2], bf[1][3]);
            }
        }
        __syncthreads();
        if (tid == 0 && c + NSTAGE < NCHUNK) {
            MBAR_EXPECT_TX(sbase + SM_MBAR + 8 * s, STAGE_BYTES);
            BULK_CP(sbase + s * STAGE_BYTES,
                    (const char*)g_wh + (size_t)(c + NSTAGE) * B_CH_BYTES,
                    B_CH_BYTES, sbase + SM_MBAR + 8 * s);
            BULK_CP(sbase + s * STAGE_BYTES + B_CH_BYTES,
                    (const char*)g_ah + (size_t)(c + NSTAGE) * A_SLAB_BYTES
                        + bm * A_CTA_BYTES,
                    A_CTA_BYTES, sbase + SM_MBAR + 8 * s);
        }
    }

    // ---------------- fused LayerNorm epilogue ----------------
    float* rsum = (float*)(smem + SM_RSUM);
    float* rsq  = (float*)(smem + SM_RSQ);
    const float* sbias = (const float*)(smem + SM_BIAS);

    float2 bs2[4];
    #pragma unroll
    for (int t = 0; t < 4; t++)
        bs2[t] = *(const float2*)&sbias[32 * wid + 8 * t + 2 * qc];

    #pragma unroll
    for (int i = 0; i < 7; i++) {
        float s0 = 0, q0 = 0, s1 = 0, q1 = 0;
        #pragma unroll
        for (int t = 0; t < 4; t++) {
            float* d = acc + (i * 4 + t) * 4;
            d[0] += bs2[t].x; d[1] += bs2[t].y;
            d[2] += bs2[t].x; d[3] += bs2[t].y;
            s0 += d[0] + d[1]; q0 += d[0] * d[0] + d[1] * d[1];
            s1 += d[2] + d[3]; q1 += d[2] * d[2] + d[3] * d[3];
        }
        #pragma unroll
        for (int o = 1; o <= 2; o <<= 1) {
            s0 += __shfl_xor_sync(0xffffffffu, s0, o);
            q0 += __shfl_xor_sync(0xffffffffu, q0, o);
            s1 += __shfl_xor_sync(0xffffffffu, s1, o);
            q1 += __shfl_xor_sync(0xffffffffu, q1, o);
        }
        if (qc == 0) {
            atomicAdd(&rsum[16 * i + qr], s0);
            atomicAdd(&rsq[16 * i + qr], q0);
            atomicAdd(&rsum[16 * i + qr + 8], s1);
            atomicAdd(&rsq[16 * i + qr + 8], q1);
        }
    }
    __syncthreads();

    float* smu = (float*)(smem + SM_MU);
    float* srs = (float*)(smem + SM_RS);
    if (tid < M_CTA) {
        float mu = rsum[tid] * (1.0f / EMBED);
        float vv = rsq[tid] * (1.0f / EMBED) - mu * mu;
        smu[tid] = mu;
        srs[tid] = rsqrtf(fmaxf(vv, 0.0f) + 1e-5f);
    }
    __syncthreads();

    const float* sg = (const float*)(smem + SM_GAMMA);
    const float* sb = (const float*)(smem + SM_BETA);
    float2 g2[4], be2[4];
    #pragma unroll
    for (int t = 0; t < 4; t++) {
        g2[t]  = *(const float2*)&sg[32 * wid + 8 * t + 2 * qc];
        be2[t] = *(const float2*)&sb[32 * wid + 8 * t + 2 * qc];
    }

    #pragma unroll
    for (int i = 0; i < 7; i++) {
        const int r0 = 16 * i + qr;
        const float mu0 = smu[r0], rs0 = srs[r0];
        const float mu1 = smu[r0 + 8], rs1 = srs[r0 + 8];
        float* o0 = out + (size_t)(bm * M_CTA + r0) * EMBED + 32 * wid + 2 * qc;
        float* o1 = o0 + 8 * (size_t)EMBED;
        #pragma unroll
        for (int t = 0; t < 4; t++) {
            float* d = acc + (i * 4 + t) * 4;
            float2 w0, w1;
            w0.x = (d[0] - mu0) * rs0 * g2[t].x + be2[t].x;
            w0.y = (d[1] - mu0) * rs0 * g2[t].y + be2[t].y;
            w1.x = (d[2] - mu1) * rs1 * g2[t].x + be2[t].x;
            w1.y = (d[3] - mu1) * rs1 * g2[t].y + be2[t].y;
            *(float2*)(o0 + 8 * t) = w0;
            *(float2*)(o1 + 8 * t) = w1;
        }
    }
}

// ---------------------------------------------------------------------------
extern "C" void kernel_launch(void* const* d_in, const int* in_sizes, int n_in,
                              void* d_out, int out_size) {
    const float* images = (const float*)d_in[0];
    const float* proj_w = (const float*)d_in[1];
    const float* proj_b = (const float*)d_in[2];
    const float* ln_g   = (const float*)d_in[3];
    const float* ln_b   = (const float*)d_in[4];
    float* out = (float*)d_out;

    float* x   = out;
    float* ent = out + (size_t)M_TOTAL * EMBED;

    cudaFuncSetAttribute(gemm_ln_kernel,
                         cudaFuncAttributeMaxDynamicSharedMemorySize, SMEM_TOTAL);

    prep_kernel<<<1568 + 288, 256>>>(images, proj_w, ent);
    gemm_ln_kernel<<<N_CTAS, 384, SMEM_TOTAL>>>(proj_b, ln_g, ln_b, x);
}

// round 8
// speedup vs baseline: 5.3341x; 1.1860x over previous
#include <cuda_runtime.h>
#include <cuda_fp16.h>
#include <cstdint>

#define EMBED 384
#define IMG_HW 224
#define GRID_HW 14
#define NPATCH 196
#define M_TOTAL 12544
#define K_TOTAL 768
#define CHAN_STRIDE 50176
#define M_CTA 32
#define G_CTAS 392               // M_TOTAL / 32
#define E_CTAS 1568              // M_TOTAL / 8
#define NCHUNK 24

// B: fp16, chunk-major, ldmatrix-swizzled: halfs c*12288 + n*32 + (seg^((n>>1)&3))*8 + k7
__device__ __half g_wh[NCHUNK * EMBED * 32];

#define B_CH_BYTES 24576         // 384*64
#define A_BUF_BYTES 2048         // 32*64
// ---- dynamic smem layout (bytes) ----
#define SM_B0    0               // 3 B stages
#define SM_A0    73728           // 2 A bufs
#define SM_BIAS  77824
#define SM_GAMMA 79360
#define SM_BETA  80896
#define SM_RSUM  82432           // 32 f
#define SM_RSQ   82560
#define SM_MU    82688
#define SM_RS    82816
#define SM_MBAR  82944           // 3 x 8B
#define SMEM_TOTAL 83072

__device__ __forceinline__ uint32_t smem_u32(const void* p) {
    uint32_t a;
    asm("{ .reg .u64 t; cvta.to.shared.u64 t, %1; cvt.u32.u64 %0, t; }"
        : "=r"(a) : "l"(p));
    return a;
}
__device__ __forceinline__ uint32_t pack2(float a, float b) {
    __half2 h = __floats2half2_rn(a, b);
    return *reinterpret_cast<uint32_t*>(&h);
}

#define MBAR_INIT(addr, cnt) \
    asm volatile("mbarrier.init.shared.b64 [%0], %1;" :: "r"(addr), "r"(cnt) : "memory")
#define MBAR_EXPECT_TX(addr, bytes) \
    asm volatile("mbarrier.arrive.expect_tx.shared.b64 _, [%0], %1;" \
                 :: "r"(addr), "r"(bytes) : "memory")
#define BULK_CP(dst, src, bytes, mbar) \
    asm volatile("cp.async.bulk.shared::cta.global.mbarrier::complete_tx::bytes " \
                 "[%0], [%1], %2, [%3];" \
                 :: "r"(dst), "l"(src), "r"(bytes), "r"(mbar) : "memory")
#define MBAR_WAIT(addr, par) do {                                              \
    uint32_t _m = (addr); uint32_t _p = (par); uint32_t _d;                    \
    asm volatile("{\n\t.reg .pred p;\n\t"                                      \
        "mbarrier.try_wait.parity.acquire.cta.shared::cta.b64 p, [%1], %2;\n\t"\
        "selp.b32 %0, 1, 0, p;\n\t}"                                           \
        : "=r"(_d) : "r"(_m), "r"(_p) : "memory");                             \
    if (!_d) {                                                                 \
        asm volatile("{\n\t.reg .pred P1;\n\t"                                 \
            "W%=:\n\t"                                                         \
            "mbarrier.try_wait.parity.acquire.cta.shared::cta.b64 P1, [%0], %1, 0x989680;\n\t" \
            "@P1 bra.uni D%=;\n\t"                                             \
            "bra.uni W%=;\n\t"                                                 \
            "D%=:\n\t}" :: "r"(_m), "r"(_p) : "memory");                       \
    }                                                                          \
} while (0)

#define LDSM4(r0, r1, r2, r3, a) \
    asm volatile("ldmatrix.sync.aligned.m8n8.x4.shared.b16 {%0,%1,%2,%3}, [%4];" \
                 : "=r"(r0), "=r"(r1), "=r"(r2), "=r"(r3) : "r"(a))

#define MMA16816(d, a0, a1, a2, a3, b0, b1) \
    asm volatile("mma.sync.aligned.m16n8k16.row.col.f32.f16.f16.f32 " \
                 "{%0,%1,%2,%3}, {%4,%5,%6,%7}, {%8,%9}, {%0,%1,%2,%3};" \
                 : "+f"((d)[0]), "+f"((d)[1]), "+f"((d)[2]), "+f"((d)[3]) \
                 : "r"(a0), "r"(a1), "r"(a2), "r"(a3), "r"(b0), "r"(b1))

// ---------------------------------------------------------------------------
// W fp16 convert: 73728 float4s, 72 blocks x 256 thr x 4 (MLP=4).
// ---------------------------------------------------------------------------
__global__ __launch_bounds__(256) void wcvt_kernel(const float* __restrict__ w) {
    #pragma unroll
    for (int r = 0; r < 4; r++) {
        int i = blockIdx.x * 256 + threadIdx.x + r * 18432;
        int n = i / 192;
        int k = (i % 192) * 4;
        float4 v = *(const float4*)(w + (size_t)n * K_TOTAL + k);
        int c = k >> 5;
        int kin = k & 31;
        int phys = (kin >> 3) ^ ((n >> 1) & 3);
        uint32_t* dst = (uint32_t*)(g_wh + c * 12288 + n * 32 + phys * 8 + (kin & 7));
        dst[0] = pack2(v.x, v.y);
        dst[1] = pack2(v.z, v.w);
    }
}

// ---------------------------------------------------------------------------
// Fused kernel: gemm+LN blocks interleaved with entropy blocks.
//   bid [0,148)      -> gemm g=bid
//   bid [148,296)    -> entropy e=bid-148
//   bid [296,540)    -> gemm g=bid-148
//   bid [540,1960)   -> entropy e=bid-392
// ---------------------------------------------------------------------------
__global__ __launch_bounds__(256, 2) void fused_kernel(
    const float* __restrict__ img, const float* __restrict__ bias,
    const float* __restrict__ gamma, const float* __restrict__ beta,
    float* __restrict__ out, float* __restrict__ ent) {
    extern __shared__ char smem[];
    const int bid = blockIdx.x;
    const int tid = threadIdx.x;
    const int wid = tid >> 5;
    const int lid = tid & 31;

    const bool is_gemm = (bid < 148) || (bid >= 296 && bid < 540);

    if (!is_gemm) {
        // ------------------------- entropy -------------------------
        const int e = (bid < 296) ? (bid - 148) : (bid - 392);
        uint32_t (*qbuf)[64] = (uint32_t(*)[64])smem;
        const int m = e * 8 + wid;
        const int b = m / NPATCH;
        const int pidx = m % NPATCH;
        const int gh = pidx / GRID_HW;
        const int gw = pidx % GRID_HW;
        const int prow = lid >> 1;
        const int pcol = (lid & 1) * 8;

        const size_t base = (size_t)(b * 3) * CHAN_STRIDE
                          + (size_t)(gh * 16 + prow) * IMG_HW + (gw * 16 + pcol);
        float4 a0 = *(const float4*)(img + base);
        float4 a1 = *(const float4*)(img + base + 4);
        float4 b0 = *(const float4*)(img + base + CHAN_STRIDE);
        float4 b1 = *(const float4*)(img + base + CHAN_STRIDE + 4);
        float4 c0 = *(const float4*)(img + base + 2 * CHAN_STRIDE);
        float4 c1 = *(const float4*)(img + base + 2 * CHAN_STRIDE + 4);

        float g[8];
        g[0] = (a0.x + b0.x + c0.x) / 3.0f;
        g[1] = (a0.y + b0.y + c0.y) / 3.0f;
        g[2] = (a0.z + b0.z + c0.z) / 3.0f;
        g[3] = (a0.w + b0.w + c0.w) / 3.0f;
        g[4] = (a1.x + b1.x + c1.x) / 3.0f;
        g[5] = (a1.y + b1.y + c1.y) / 3.0f;
        g[6] = (a1.z + b1.z + c1.z) / 3.0f;
        g[7] = (a1.w + b1.w + c1.w) / 3.0f;

        uint32_t q[8];
        #pragma unroll
        for (int i = 0; i < 8; i++)
            q[i] = (uint32_t)(int)fminf(fmaxf(g[i] * 31.0f, 0.0f), 31.0f);
        qbuf[wid][lid * 2]     = q[0] | (q[1] << 8) | (q[2] << 16) | (q[3] << 24);
        qbuf[wid][lid * 2 + 1] = q[4] | (q[5] << 8) | (q[6] << 16) | (q[7] << 24);
        __syncwarp();

        const uint32_t pat = 0x01010101u * (uint32_t)lid;
        int bits = 0;
        #pragma unroll
        for (int i = 0; i < 64; i++) bits += __popc(__vcmpeq4(qbuf[wid][i], pat));

        float p = (float)(bits >> 3) * (1.0f / 256.0f);
        float t = p * log2f(p + 1e-10f);
        #pragma unroll
        for (int o = 16; o; o >>= 1) t += __shfl_xor_sync(0xffffffffu, t, o);
        if (lid == 0) ent[m] = -t * 0.2f;
        return;
    }

    // ---------------------------- gemm + LN ----------------------------
    const int bm = (bid < 148) ? bid : (bid - 148);
    const uint32_t sbase = smem_u32(smem);
    const int qr = lid >> 2;
    const int qc = lid & 3;

    if (tid < 32) {
        ((float*)(smem + SM_RSUM))[tid] = 0.0f;
        ((float*)(smem + SM_RSQ))[tid]  = 0.0f;
    }
    if (tid >= 32 && tid < 32 + 96) {
        int i4 = tid - 32;   // 96 float4s = 384 floats
        ((float4*)(smem + SM_BIAS))[i4]  = ((const float4*)bias)[i4];
        ((float4*)(smem + SM_GAMMA))[i4] = ((const float4*)gamma)[i4];
        ((float4*)(smem + SM_BETA))[i4]  = ((const float4*)beta)[i4];
    }
    if (tid == 0) {
        #pragma unroll
        for (int s = 0; s < 3; s++) {
            MBAR_INIT(sbase + SM_MBAR + 8 * s, 1);
            MBAR_EXPECT_TX(sbase + SM_MBAR + 8 * s, B_CH_BYTES);
            BULK_CP(sbase + s * B_CH_BYTES,
                    (const char*)g_wh + (size_t)s * B_CH_BYTES, B_CH_BYTES,
                    sbase + SM_MBAR + 8 * s);
        }
    }

    // A gather geometry: 1 float4 per thread per chunk.
    const int arow = tid >> 3;       // 0..31
    const int aj = tid & 7;          // float4 slot
    const float* abase;
    {
        int m = bm * M_CTA + arow;
        abase = img + (size_t)((m / NPATCH) * 3) * CHAN_STRIDE
              + (size_t)(((m % NPATCH) / GRID_HW) * 16) * IMG_HW
              + ((m % NPATCH) % GRID_HW) * 16;
    }
    const uint32_t adst = arow * 64 + (((aj >> 1) ^ ((arow >> 1) & 3)) << 4)
                        + (aj & 1) * 8;
    auto aoff = [&](int c) -> size_t {
        int k = c * 32 + 4 * aj;
        return (size_t)(k >> 8) * CHAN_STRIDE + ((k >> 4) & 15) * IMG_HW + (k & 15);
    };

    // Prologue: A(0) -> buf0; A(1) -> regs.
    float4 areg;
    {
        float4 v = *(const float4*)(abase + aoff(0));
        *(uint2*)(smem + SM_A0 + adst) = make_uint2(pack2(v.x, v.y), pack2(v.z, v.w));
        areg = *(const float4*)(abase + aoff(1));
    }
    __syncthreads();

    float acc[48];
    #pragma unroll
    for (int i = 0; i < 48; i++) acc[i] = 0.0f;

    // lane geometry (ldmatrix)
    const int a_row = ((lid >> 3) & 1) * 8 + (lid & 7);
    const int a_kbit = lid >> 4;
    const int b_noff = ((lid >> 4) & 1) * 8 + (lid & 7);
    const int b_segbit = (lid >> 3) & 1;
    const int xr = (lid & 7) >> 1;

    int s = 0, par = 0, c3 = 0;      // stage, parity, c/3 tracker
    for (int c = 0; c < NCHUNK; c++) {
        MBAR_WAIT(sbase + SM_MBAR + 8 * s, par);

        // Store A(c+1); prefetch A(c+2).
        if (c + 1 < NCHUNK) {
            *(uint2*)(smem + SM_A0 + ((c + 1) & 1) * A_BUF_BYTES + adst) =
                make_uint2(pack2(areg.x, areg.y), pack2(areg.z, areg.w));
            if (c + 2 < NCHUNK) areg = *(const float4*)(abase + aoff(c + 2));
        }

        const uint32_t Bst = sbase + s * B_CH_BYTES;
        const uint32_t Ast = sbase + SM_A0 + (c & 1) * A_BUF_BYTES;
        #pragma unroll
        for (int sh = 0; sh < 2; sh++) {
            uint32_t bf[3][4];
            const int sg = (2 * sh + b_segbit) ^ xr;
            #pragma unroll
            for (int tp = 0; tp < 3; tp++) {
                int n = 48 * wid + 16 * tp + b_noff;
                LDSM4(bf[tp][0], bf[tp][1], bf[tp][2], bf[tp][3],
                      Bst + n * 64 + sg * 16);
            }
            const int aseg = (2 * sh + a_kbit) ^ xr;
            #pragma unroll
            for (int i = 0; i < 2; i++) {
                uint32_t a0, a1, a2, a3;
                LDSM4(a0, a1, a2, a3, Ast + (16 * i + a_row) * 64 + aseg * 16);
                #pragma unroll
                for (int tp = 0; tp < 3; tp++) {
                    MMA16816(acc + (i * 6 + 2 * tp) * 4, a0, a1, a2, a3,
                             bf[tp][0], bf[tp][1]);
                    MMA16816(acc + (i * 6 + 2 * tp + 1) * 4, a0, a1, a2, a3,
                             bf[tp][2], bf[tp][3]);
                }
            }
        }
        __syncthreads();
        if (tid == 0 && c + 3 < NCHUNK) {
            MBAR_EXPECT_TX(sbase + SM_MBAR + 8 * s, B_CH_BYTES);
            BULK_CP(sbase + s * B_CH_BYTES,
                    (const char*)g_wh + (size_t)(c + 3) * B_CH_BYTES,
                    B_CH_BYTES, sbase + SM_MBAR + 8 * s);
        }
        if (++s == 3) { s = 0; }
        if (++c3 == 3) { c3 = 0; par ^= 1; }
    }

    // ---------------- fused LayerNorm epilogue ----------------
    float* rsum = (float*)(smem + SM_RSUM);
    float* rsq  = (float*)(smem + SM_RSQ);
    const float* sbias = (const float*)(smem + SM_BIAS);

    float2 bs2[6];
    #pragma unroll
    for (int t = 0; t < 6; t++)
        bs2[t] = *(const float2*)&sbias[48 * wid + 8 * t + 2 * qc];

    #pragma unroll
    for (int i = 0; i < 2; i++) {
        float s0 = 0, q0 = 0, s1 = 0, q1 = 0;
        #pragma unroll
        for (int t = 0; t < 6; t++) {
            float* d = acc + (i * 6 + t) * 4;
            d[0] += bs2[t].x; d[1] += bs2[t].y;
            d[2] += bs2[t].x; d[3] += bs2[t].y;
            s0 += d[0] + d[1]; q0 += d[0] * d[0] + d[1] * d[1];
            s1 += d[2] + d[3]; q1 += d[2] * d[2] + d[3] * d[3];
        }
        #pragma unroll
        for (int o = 1; o <= 2; o <<= 1) {
            s0 += __shfl_xor_sync(0xffffffffu, s0, o);
            q0 += __shfl_xor_sync(0xffffffffu, q0, o);
            s1 += __shfl_xor_sync(0xffffffffu, s1, o);
            q1 += __shfl_xor_sync(0xffffffffu, q1, o);
        }
        if (qc == 0) {
            atomicAdd(&rsum[16 * i + qr], s0);
            atomicAdd(&rsq[16 * i + qr], q0);
            atomicAdd(&rsum[16 * i + qr + 8], s1);
            atomicAdd(&rsq[16 * i + qr + 8], q1);
        }
    }
    __syncthreads();

    float* smu = (float*)(smem + SM_MU);
    float* srs = (float*)(smem + SM_RS);
    if (tid < 32) {
        float mu = rsum[tid] * (1.0f / EMBED);
        float vv = rsq[tid] * (1.0f / EMBED) - mu * mu;
        smu[tid] = mu;
        srs[tid] = rsqrtf(fmaxf(vv, 0.0f) + 1e-5f);
    }
    __syncthreads();

    const float* sg = (const float*)(smem + SM_GAMMA);
    const float* sb = (const float*)(smem + SM_BETA);
    float2 g2[6], be2[6];
    #pragma unroll
    for (int t = 0; t < 6; t++) {
        g2[t]  = *(const float2*)&sg[48 * wid + 8 * t + 2 * qc];
        be2[t] = *(const float2*)&sb[48 * wid + 8 * t + 2 * qc];
    }

    #pragma unroll
    for (int i = 0; i < 2; i++) {
        const int r0 = 16 * i + qr;
        const float mu0 = smu[r0], rs0 = srs[r0];
        const float mu1 = smu[r0 + 8], rs1 = srs[r0 + 8];
        float* o0 = out + (size_t)(bm * M_CTA + r0) * EMBED + 48 * wid + 2 * qc;
        float* o1 = o0 + 8 * (size_t)EMBED;
        #pragma unroll
        for (int t = 0; t < 6; t++) {
            float* d = acc + (i * 6 + t) * 4;
            float2 w0, w1;
            w0.x = (d[0] - mu0) * rs0 * g2[t].x + be2[t].x;
            w0.y = (d[1] - mu0) * rs0 * g2[t].y + be2[t].y;
            w1.x = (d[2] - mu1) * rs1 * g2[t].x + be2[t].x;
            w1.y = (d[3] - mu1) * rs1 * g2[t].y + be2[t].y;
            *(float2*)(o0 + 8 * t) = w0;
            *(float2*)(o1 + 8 * t) = w1;
        }
    }
}

// ---------------------------------------------------------------------------
extern "C" void kernel_launch(void* const* d_in, const int* in_sizes, int n_in,
                              void* d_out, int out_size) {
    const float* images = (const float*)d_in[0];
    const float* proj_w = (const float*)d_in[1];
    const float* proj_b = (const float*)d_in[2];
    const float* ln_g   = (const float*)d_in[3];
    const float* ln_b   = (const float*)d_in[4];
    float* out = (float*)d_out;

    float* x   = out;
    float* ent = out + (size_t)M_TOTAL * EMBED;

    cudaFuncSetAttribute(fused_kernel,
                         cudaFuncAttributeMaxDynamicSharedMemorySize, SMEM_TOTAL);

    wcvt_kernel<<<72, 256>>>(proj_w);
    fused_kernel<<<G_CTAS + E_CTAS, 256, SMEM_TOTAL>>>(images, proj_b, ln_g,
                                                       ln_b, x, ent);
}